// round 12
// baseline (speedup 1.0000x reference)
#include <cuda_runtime.h>

#define NP  500000
#define NC  1000
#define DIM 128
#define NB  148                       // one partition block per SM
#define CH  3384                      // points per chunk (mult of 8; 148*3384 >= NP)
#define PT  8                         // points per thread in blockhist
#define CAP 4096                      // per-class slot capacity in g_sorted
#define SHI 1024                      // smem-staged indices per class (mean 500, +23 sigma)

// Scratch (no allocations allowed -> __device__ globals)
__device__ int      g_counts[NC];
__device__ int      g_bh[NB * NC];    // per-block histogram, block-major
__device__ int      g_bb[NB * NC];    // per-(block,class) LOCAL base
__device__ unsigned g_combo[NP];      // (class << 12) | rank-within-(block,class)
__device__ int      g_sorted[NC * CAP]; // slotted: class c owns [c*CAP, c*CAP+count)
__device__ unsigned g_arrive;         // grid-barrier arrival counter
__device__ unsigned g_release;        // grid-barrier epoch (monotonic across replays)

// ---------------------------------------------------------------------------
// In-block dtype probe: y int64 (LE) => all odd 32-bit words of the first 256
// words are zero (classes < 1000). P(false positive | int32) ~ 1000^-128.
// ---------------------------------------------------------------------------
__device__ __forceinline__ int probe_is64(const int* __restrict__ y32, int* sflag) {
    if (threadIdx.x == 0) *sflag = 0;
    __syncthreads();
    if (threadIdx.x < 128) {
        int nz = (y32[2 * threadIdx.x + 1] != 0);
        unsigned any = __ballot_sync(0xFFFFFFFF, nz);
        if ((threadIdx.x & 31) == 0 && any) atomicOr(sflag, 1);
    }
    __syncthreads();
    return (*sflag == 0) ? 1 : 0;   // no nonzero odd words -> int64
}

// Load 8 consecutive class ids starting at point index p (p % 8 == 0).
__device__ __forceinline__ void load_classes8(const int* __restrict__ y32, int shift,
                                              int p, int c[PT]) {
    if (shift) {            // int64: element i at y32[2i]; 8 elems = 4 x int4
        const int4* q = (const int4*)(y32 + 2 * p);
        int4 v0 = q[0], v1 = q[1], v2 = q[2], v3 = q[3];
        c[0] = v0.x; c[1] = v0.z; c[2] = v1.x; c[3] = v1.z;
        c[4] = v2.x; c[5] = v2.z; c[6] = v3.x; c[7] = v3.z;
    } else {                // int32: 8 elems = 2 x int4
        const int4* q = (const int4*)(y32 + p);
        int4 v0 = q[0], v1 = q[1];
        c[0] = v0.x; c[1] = v0.y; c[2] = v0.z; c[3] = v0.w;
        c[4] = v1.x; c[5] = v1.y; c[6] = v1.z; c[7] = v1.w;
    }
}

// ---------------------------------------------------------------------------
// Kernel 1 (FUSED): phase A = per-block histogram + combo ranks (as before);
// software grid barrier; phase B = per-class scan of block counts (one warp
// per class, 2368 warps cover 1000 classes) producing g_bb + g_counts.
//
// Grid barrier: epoch protocol. Every block reads the g_release base BEFORE
// arriving (so reads always precede the bump, which needs all NB arrivals);
// the last arriver resets g_arrive and bumps the epoch. Works unchanged
// across graph replays because targets are relative to the entry-read base.
// All 148 blocks are co-resident (1/SM) -> no deadlock.
// ---------------------------------------------------------------------------
__global__ void __launch_bounds__(512) histscan_kernel(const int* __restrict__ y32) {
    __shared__ int h[NC];
    __shared__ int sflag;
    __shared__ unsigned sbase;

    if (threadIdx.x == 0) sbase = atomicAdd(&g_release, 0u);  // entry epoch
    const int shift = probe_is64(y32, &sflag);
    for (int c = threadIdx.x; c < NC; c += 512) h[c] = 0;
    __syncthreads();

    // ---- Phase A: histogram + ranks ----
    const int b     = blockIdx.x;
    const int start = b * CH;
    const int end   = (start + CH < NP) ? start + CH : NP;   // (end-start) % 8 == 0
    const int seg   = start + threadIdx.x * PT;

    if (seg < end) {
        int c[PT];
        load_classes8(y32, shift, seg, c);
        unsigned cb[PT];
        #pragma unroll
        for (int k = 0; k < PT; k++) {
            unsigned r = (unsigned)atomicAdd(&h[c[k]], 1);
            cb[k] = ((unsigned)c[k] << 12) | r;   // rank < 3384 < 4096
        }
        uint4 p0 = make_uint4(cb[0], cb[1], cb[2], cb[3]);
        uint4 p1 = make_uint4(cb[4], cb[5], cb[6], cb[7]);
        ((uint4*)(g_combo + seg))[0] = p0;
        ((uint4*)(g_combo + seg))[1] = p1;
    }
    __syncthreads();
    for (int c = threadIdx.x; c < NC; c += 512)
        g_bh[b * NC + c] = h[c];

    // ---- Grid barrier ----
    __syncthreads();                       // all smem/global work of A issued
    if (threadIdx.x == 0) {
        __threadfence();                   // publish this block's g_bh row
        unsigned t = atomicAdd(&g_arrive, 1u);
        if (t == NB - 1) {
            atomicExch(&g_arrive, 0u);     // reset for next replay
            __threadfence();
            atomicAdd(&g_release, 1u);     // release everyone
        } else {
            while (atomicAdd(&g_release, 0u) < sbase + 1u) { }
        }
        __threadfence();                   // acquire: see all blocks' g_bh
    }
    __syncthreads();

    // ---- Phase B: per-class scan over NB block counts (1 warp / class) ----
    const int lane = threadIdx.x & 31;
    const int wid  = threadIdx.x >> 5;                 // 16 warps
    const int c    = blockIdx.x * 16 + wid;            // global warp id = class
    if (c < NC) {
        const int b0 = lane * 5;                       // 5 contiguous blocks/lane
        int v[5];
        int sum = 0;
        #pragma unroll
        for (int j = 0; j < 5; j++) {
            int bb = b0 + j;
            v[j] = (bb < NB) ? g_bh[bb * NC + c] : 0;
            sum += v[j];
        }
        int s = sum;                                   // warp inclusive scan
        #pragma unroll
        for (int o = 1; o < 32; o <<= 1) {
            int n = __shfl_up_sync(0xFFFFFFFF, s, o);
            if (lane >= o) s += n;
        }
        int run = s - sum;                             // exclusive prefix
        #pragma unroll
        for (int j = 0; j < 5; j++) {
            int bb = b0 + j;
            if (bb < NB) { g_bb[bb * NC + c] = run; run += v[j]; }
        }
        if (lane == 31) g_counts[c] = s;               // class total
    }
}

// ---------------------------------------------------------------------------
// Kernel 2: scatter, 2 points/thread for max occupancy (~250k threads, ~53
// warps/SM -- latency hidden by warp supply). One coalesced uint2 combo load,
// two L1-hit base lookups (warp shares one 4KB g_bb row), two fire-and-forget
// scattered stores into the slotted layout. No atomics, no smem, no barrier.
// ---------------------------------------------------------------------------
__global__ void __launch_bounds__(256) scatter_kernel() {
    const int seg = (blockIdx.x * 256 + threadIdx.x) * 2;
    if (seg >= NP) return;
    const int b = seg / CH;               // both points in same chunk (CH even)

    uint2 p = *(const uint2*)(g_combo + seg);
    int c0 = (int)(p.x >> 12), r0 = (int)(p.x & 0xFFFu);
    int c1 = (int)(p.y >> 12), r1 = (int)(p.y & 0xFFFu);
    int b0 = __ldg(&g_bb[b * NC + c0]);
    int b1 = __ldg(&g_bb[b * NC + c1]);
    g_sorted[c0 * CAP + b0 + r0] = seg;
    g_sorted[c1 * CAP + b1 + r1] = seg + 1;
}

// ---------------------------------------------------------------------------
// Kernel 3: one block per class, depth-8 pipeline, 4 blocks/SM. Class index
// list cooperatively staged into SMEM so the main loop's idx fetches are LDS
// and each iteration exposes ONE DRAM latency (the 8 independent x-row
// loads). Overflow beyond SHI (>23 sigma) falls back to global reads.
// ---------------------------------------------------------------------------
__global__ void __launch_bounds__(256, 4) mean_kernel(
    const float* __restrict__ x,
    const float* __restrict__ centers,
    const float* __restrict__ counter,
    float*       __restrict__ out)
{
    __shared__ int    sidx[SHI];
    __shared__ float4 sh[8][32];

    const int c    = blockIdx.x;
    const int cnt  = g_counts[c];
    const int off  = c * CAP;             // slotted layout: fixed class region
    const int lane = threadIdx.x & 31;
    const int grp  = threadIdx.x >> 5;

    const int nsh = (cnt < SHI) ? cnt : SHI;
    for (int i = threadIdx.x; i < nsh; i += 256)
        sidx[i] = g_sorted[off + i];
    __syncthreads();

    float4 acc = make_float4(0.f, 0.f, 0.f, 0.f);

    int r = grp;
    // main loop: 8 rows in flight per warp, idx from smem
    for (; r + 56 < nsh; r += 64) {
        int idx[8];
        #pragma unroll
        for (int k = 0; k < 8; k++) idx[k] = sidx[r + 8 * k];
        #pragma unroll
        for (int k = 0; k < 8; k++) {
            float4 v = __ldcs(&((const float4*)(x + (size_t)idx[k] * DIM))[lane]);
            acc.x += v.x; acc.y += v.y; acc.z += v.z; acc.w += v.w;
        }
    }
    // mid tail: 4 rows in flight
    for (; r + 24 < nsh; r += 32) {
        int idx[4];
        #pragma unroll
        for (int k = 0; k < 4; k++) idx[k] = sidx[r + 8 * k];
        #pragma unroll
        for (int k = 0; k < 4; k++) {
            float4 v = __ldcs(&((const float4*)(x + (size_t)idx[k] * DIM))[lane]);
            acc.x += v.x; acc.y += v.y; acc.z += v.z; acc.w += v.w;
        }
    }
    // final tail (smem range)
    for (; r < nsh; r += 8) {
        float4 v = __ldcs(&((const float4*)(x + (size_t)sidx[r] * DIM))[lane]);
        acc.x += v.x; acc.y += v.y; acc.z += v.z; acc.w += v.w;
    }
    // overflow tail (cnt > SHI; statistically never, correctness guarantee)
    for (; r < cnt; r += 8) {
        int i = g_sorted[off + r];
        float4 v = __ldcs(&((const float4*)(x + (size_t)i * DIM))[lane]);
        acc.x += v.x; acc.y += v.y; acc.z += v.z; acc.w += v.w;
    }

    sh[grp][lane] = acc;
    __syncthreads();

    if (grp == 0) {
        float4 s = sh[0][lane];
        #pragma unroll
        for (int g = 1; g < 8; g++) {
            float4 v = sh[g][lane];
            s.x += v.x; s.y += v.y; s.z += v.z; s.w += v.w;
        }
        float4 cv = ((const float4*)(centers + c * DIM))[lane];
        float4 o;
        if (cnt > 0) {
            float ctr = counter[0];
            float inv = 1.0f / (ctr + 1.0f);
            float rn  = 1.0f / (float)cnt;
            o.x = (s.x * rn + cv.x * ctr) * inv;
            o.y = (s.y * rn + cv.y * ctr) * inv;
            o.z = (s.z * rn + cv.z * ctr) * inv;
            o.w = (s.w * rn + cv.w * ctr) * inv;
        } else {
            o = cv;  // class absent from batch: keep old center
        }
        ((float4*)(out + c * DIM))[lane] = o;
    }
}

// ---------------------------------------------------------------------------
// kernel_launch: graph-capturable, allocation-free, deterministic.
// Inputs (metadata order): x[NP*DIM] f32, y[NP] int64/int32, centers[NC*DIM]
// f32, counter[1] f32. Output: new centers [NC*DIM] f32.
// ---------------------------------------------------------------------------
extern "C" void kernel_launch(void* const* d_in, const int* in_sizes, int n_in,
                              void* d_out, int out_size) {
    const float* x       = (const float*)d_in[0];
    const int*   y32     = (const int*)d_in[1];
    const float* centers = (const float*)d_in[2];
    const float* counter = (const float*)d_in[3];
    float*       out     = (float*)d_out;

    histscan_kernel<<<NB, 512>>>(y32);
    scatter_kernel<<<(NP / 2 + 255) / 256, 256>>>();
    mean_kernel<<<NC, 256>>>(x, centers, counter, out);
}

// round 13
// speedup vs baseline: 1.0435x; 1.0435x over previous
#include <cuda_runtime.h>

#define NP  500000
#define NC  1000
#define DIM 128
#define NB  148                       // one partition block per SM
#define CH  3384                      // points per chunk (mult of 8; 148*3384 >= NP)
#define PT  8                         // points per thread in blockhist
#define CAP 4096                      // per-class slot capacity in g_sorted
#define SHI 1024                      // smem-staged indices per class (mean 500, +23 sigma)

// Scratch (no allocations allowed -> __device__ globals)
__device__ int      g_counts[NC];
__device__ int      g_bh[NB * NC];    // per-block histogram, block-major
__device__ int      g_bb[NB * NC];    // per-(block,class) LOCAL base
__device__ unsigned g_combo[NP];      // (class << 12) | rank-within-(block,class)
__device__ int      g_sorted[NC * CAP]; // slotted: class c owns [c*CAP, c*CAP+count)

// ---------------------------------------------------------------------------
// In-block dtype probe: y int64 (LE) => all odd 32-bit words of the first 256
// words are zero (classes < 1000). P(false positive | int32) ~ 1000^-128.
// ---------------------------------------------------------------------------
__device__ __forceinline__ int probe_is64(const int* __restrict__ y32, int* sflag) {
    if (threadIdx.x == 0) *sflag = 0;
    __syncthreads();
    if (threadIdx.x < 128) {
        int nz = (y32[2 * threadIdx.x + 1] != 0);
        unsigned any = __ballot_sync(0xFFFFFFFF, nz);
        if ((threadIdx.x & 31) == 0 && any) atomicOr(sflag, 1);
    }
    __syncthreads();
    return (*sflag == 0) ? 1 : 0;   // no nonzero odd words -> int64
}

// Load 8 consecutive class ids starting at point index p (p % 8 == 0).
__device__ __forceinline__ void load_classes8(const int* __restrict__ y32, int shift,
                                              int p, int c[PT]) {
    if (shift) {            // int64: element i at y32[2i]; 8 elems = 4 x int4
        const int4* q = (const int4*)(y32 + 2 * p);
        int4 v0 = q[0], v1 = q[1], v2 = q[2], v3 = q[3];
        c[0] = v0.x; c[1] = v0.z; c[2] = v1.x; c[3] = v1.z;
        c[4] = v2.x; c[5] = v2.z; c[6] = v3.x; c[7] = v3.z;
    } else {                // int32: 8 elems = 2 x int4
        const int4* q = (const int4*)(y32 + p);
        int4 v0 = q[0], v1 = q[1];
        c[0] = v0.x; c[1] = v0.y; c[2] = v0.z; c[3] = v0.w;
        c[4] = v1.x; c[5] = v1.y; c[6] = v1.z; c[7] = v1.w;
    }
}

// ---------------------------------------------------------------------------
// Kernel 1: per-block histogram, batched 8 points/thread. atomicAdd return
// value = rank within (block,class). Pack (class,rank) into one u32 combo so
// downstream passes never re-read y. Two uint4 stores per thread (coalesced).
// ---------------------------------------------------------------------------
__global__ void __launch_bounds__(512) blockhist_kernel(const int* __restrict__ y32) {
    __shared__ int h[NC];
    __shared__ int sflag;
    const int shift = probe_is64(y32, &sflag);
    for (int c = threadIdx.x; c < NC; c += 512) h[c] = 0;
    __syncthreads();

    const int b     = blockIdx.x;
    const int start = b * CH;
    const int end   = (start + CH < NP) ? start + CH : NP;   // (end-start) % 8 == 0
    const int seg   = start + threadIdx.x * PT;

    if (seg < end) {
        int c[PT];
        load_classes8(y32, shift, seg, c);
        unsigned cb[PT];
        #pragma unroll
        for (int k = 0; k < PT; k++) {
            unsigned r = (unsigned)atomicAdd(&h[c[k]], 1);
            cb[k] = ((unsigned)c[k] << 12) | r;   // rank < 3384 < 4096
        }
        uint4 p0 = make_uint4(cb[0], cb[1], cb[2], cb[3]);
        uint4 p1 = make_uint4(cb[4], cb[5], cb[6], cb[7]);
        ((uint4*)(g_combo + seg))[0] = p0;
        ((uint4*)(g_combo + seg))[1] = p1;
    }
    __syncthreads();
    for (int c = threadIdx.x; c < NC; c += 512)
        g_bh[b * NC + c] = h[c];
}

// ---------------------------------------------------------------------------
// Kernel 2: block-per-class parallel scan over the NB=148 block counts.
// 160 threads (5 warps); shfl warp-scan + cross-warp combine -> local
// exclusive base g_bb[t][c] and class total g_counts[c]. Slotted output
// layout means there is NO cross-class prefix anywhere.
// ---------------------------------------------------------------------------
__global__ void __launch_bounds__(160) blockscan_kernel() {
    const int c    = blockIdx.x;
    const int t    = threadIdx.x;          // = block index b (when < NB)
    const int lane = t & 31;
    const int w    = t >> 5;               // 5 warps

    int v = (t < NB) ? g_bh[t * NC + c] : 0;

    int s = v;
    #pragma unroll
    for (int o = 1; o < 32; o <<= 1) {
        int n = __shfl_up_sync(0xFFFFFFFF, s, o);
        if (lane >= o) s += n;
    }

    __shared__ int wsum[5];
    __shared__ int wbase[5];
    if (lane == 31) wsum[w] = s;
    __syncthreads();

    if (w == 0 && lane < 5) {
        int ws = wsum[lane];
        int sc = ws;
        #pragma unroll
        for (int o = 1; o < 8; o <<= 1) {
            int n = __shfl_up_sync(0x0000001F, sc, o);
            if (lane >= o) sc += n;
        }
        wbase[lane] = sc - ws;             // exclusive warp base
        if (lane == 4) g_counts[c] = sc;   // class total
    }
    __syncthreads();

    if (t < NB)
        g_bb[t * NC + c] = (s - v) + wbase[w]; // local exclusive prefix
}

// ---------------------------------------------------------------------------
// Kernel 3: scatter, 4 points/thread: one coalesced uint4 combo load (single
// LDG.128 per thread), four L1-hit base lookups (warp shares one 4KB g_bb
// row), four fire-and-forget scattered stores. ~125k threads (~27 warps/SM)
// still hides latency; half the issue count of the PT=2 version.
// ---------------------------------------------------------------------------
__global__ void __launch_bounds__(256) scatter_kernel() {
    const int seg = (blockIdx.x * 256 + threadIdx.x) * 4;
    if (seg >= NP) return;
    const int b = seg / CH;               // all 4 points in same chunk (CH % 8 == 0)

    uint4 p = *(const uint4*)(g_combo + seg);
    int c0 = (int)(p.x >> 12), r0 = (int)(p.x & 0xFFFu);
    int c1 = (int)(p.y >> 12), r1 = (int)(p.y & 0xFFFu);
    int c2 = (int)(p.z >> 12), r2 = (int)(p.z & 0xFFFu);
    int c3 = (int)(p.w >> 12), r3 = (int)(p.w & 0xFFFu);
    int b0 = __ldg(&g_bb[b * NC + c0]);
    int b1 = __ldg(&g_bb[b * NC + c1]);
    int b2 = __ldg(&g_bb[b * NC + c2]);
    int b3 = __ldg(&g_bb[b * NC + c3]);
    g_sorted[c0 * CAP + b0 + r0] = seg;
    g_sorted[c1 * CAP + b1 + r1] = seg + 1;
    g_sorted[c2 * CAP + b2 + r2] = seg + 2;
    g_sorted[c3 * CAP + b3 + r3] = seg + 3;
}

// ---------------------------------------------------------------------------
// Kernel 4: one block per class, depth-8 pipeline, 4 blocks/SM. Class index
// list cooperatively staged into SMEM so the main loop's idx fetches are LDS
// and each iteration exposes ONE DRAM latency (the 8 independent x-row
// loads). Overflow beyond SHI (>23 sigma) falls back to global reads.
// ---------------------------------------------------------------------------
__global__ void __launch_bounds__(256, 4) mean_kernel(
    const float* __restrict__ x,
    const float* __restrict__ centers,
    const float* __restrict__ counter,
    float*       __restrict__ out)
{
    __shared__ int    sidx[SHI];
    __shared__ float4 sh[8][32];

    const int c    = blockIdx.x;
    const int cnt  = g_counts[c];
    const int off  = c * CAP;             // slotted layout: fixed class region
    const int lane = threadIdx.x & 31;
    const int grp  = threadIdx.x >> 5;

    const int nsh = (cnt < SHI) ? cnt : SHI;
    for (int i = threadIdx.x; i < nsh; i += 256)
        sidx[i] = g_sorted[off + i];
    __syncthreads();

    float4 acc = make_float4(0.f, 0.f, 0.f, 0.f);

    int r = grp;
    // main loop: 8 rows in flight per warp, idx from smem
    for (; r + 56 < nsh; r += 64) {
        int idx[8];
        #pragma unroll
        for (int k = 0; k < 8; k++) idx[k] = sidx[r + 8 * k];
        #pragma unroll
        for (int k = 0; k < 8; k++) {
            float4 v = __ldcs(&((const float4*)(x + (size_t)idx[k] * DIM))[lane]);
            acc.x += v.x; acc.y += v.y; acc.z += v.z; acc.w += v.w;
        }
    }
    // mid tail: 4 rows in flight
    for (; r + 24 < nsh; r += 32) {
        int idx[4];
        #pragma unroll
        for (int k = 0; k < 4; k++) idx[k] = sidx[r + 8 * k];
        #pragma unroll
        for (int k = 0; k < 4; k++) {
            float4 v = __ldcs(&((const float4*)(x + (size_t)idx[k] * DIM))[lane]);
            acc.x += v.x; acc.y += v.y; acc.z += v.z; acc.w += v.w;
        }
    }
    // final tail (smem range)
    for (; r < nsh; r += 8) {
        float4 v = __ldcs(&((const float4*)(x + (size_t)sidx[r] * DIM))[lane]);
        acc.x += v.x; acc.y += v.y; acc.z += v.z; acc.w += v.w;
    }
    // overflow tail (cnt > SHI; statistically never, correctness guarantee)
    for (; r < cnt; r += 8) {
        int i = g_sorted[off + r];
        float4 v = __ldcs(&((const float4*)(x + (size_t)i * DIM))[lane]);
        acc.x += v.x; acc.y += v.y; acc.z += v.z; acc.w += v.w;
    }

    sh[grp][lane] = acc;
    __syncthreads();

    if (grp == 0) {
        float4 s = sh[0][lane];
        #pragma unroll
        for (int g = 1; g < 8; g++) {
            float4 v = sh[g][lane];
            s.x += v.x; s.y += v.y; s.z += v.z; s.w += v.w;
        }
        float4 cv = ((const float4*)(centers + c * DIM))[lane];
        float4 o;
        if (cnt > 0) {
            float ctr = counter[0];
            float inv = 1.0f / (ctr + 1.0f);
            float rn  = 1.0f / (float)cnt;
            o.x = (s.x * rn + cv.x * ctr) * inv;
            o.y = (s.y * rn + cv.y * ctr) * inv;
            o.z = (s.z * rn + cv.z * ctr) * inv;
            o.w = (s.w * rn + cv.w * ctr) * inv;
        } else {
            o = cv;  // class absent from batch: keep old center
        }
        ((float4*)(out + c * DIM))[lane] = o;
    }
}

// ---------------------------------------------------------------------------
// kernel_launch: graph-capturable, allocation-free, deterministic.
// Inputs (metadata order): x[NP*DIM] f32, y[NP] int64/int32, centers[NC*DIM]
// f32, counter[1] f32. Output: new centers [NC*DIM] f32.
// ---------------------------------------------------------------------------
extern "C" void kernel_launch(void* const* d_in, const int* in_sizes, int n_in,
                              void* d_out, int out_size) {
    const float* x       = (const float*)d_in[0];
    const int*   y32     = (const int*)d_in[1];
    const float* centers = (const float*)d_in[2];
    const float* counter = (const float*)d_in[3];
    float*       out     = (float*)d_out;

    blockhist_kernel<<<NB, 512>>>(y32);
    blockscan_kernel<<<NC, 160>>>();
    scatter_kernel<<<(NP / 4 + 255) / 256, 256>>>();
    mean_kernel<<<NC, 256>>>(x, centers, counter, out);
}